// round 2
// baseline (speedup 1.0000x reference)
#include <cuda_runtime.h>

// Problem constants
constexpr int CB   = 2;
constexpr int CS   = 2048;
constexpr int CH   = 1024;
constexpr int CNH  = 16;
constexpr int CNKV = 4;
constexpr int CHD  = 64;
constexpr int CM   = CB * CS;        // 4096 rows

// Scratch (no cudaMalloc allowed)
__device__ float g_q[(size_t)CB * CS * CNH * CHD];     // 16 MB
__device__ float g_k[(size_t)CB * CS * CNKV * CHD];    // 4 MB
__device__ float g_v[(size_t)CB * CS * CNKV * CHD];    // 4 MB
__device__ float g_attn[(size_t)CB * CS * CNH * CHD];  // 16 MB

// ---------------------------------------------------------------------------
// SGEMM: C = A(MxK) @ B(KxN), row-major, all dims multiples of tile sizes.
// 128x128 block tile, BK=8, 8x8 per thread (2x2 of 4-vectors), 256 threads.
// ---------------------------------------------------------------------------
__global__ __launch_bounds__(256) void sgemm_kernel(
    int M, int N, int K,
    const float* __restrict__ A, const float* __restrict__ Bm,
    float* __restrict__ C)
{
    constexpr int BM = 128, BN = 128, BK = 8;
    __shared__ float As[BK][BM];   // transposed A tile
    __shared__ float Bs[BK][BN];

    const int tid  = threadIdx.x;
    const int brow = blockIdx.y, bcol = blockIdx.x;

    A  += (size_t)brow * BM * K;
    Bm += (size_t)bcol * BN;
    C  += (size_t)brow * BM * N + (size_t)bcol * BN;

    const int tRow = tid >> 4;       // 0..15
    const int tCol = tid & 15;       // 0..15
    const int aRow = tid >> 1;       // 0..127
    const int aCol = (tid & 1) * 4;  // 0 or 4
    const int bRow = tid >> 5;       // 0..7
    const int bCol = (tid & 31) * 4; // 0..124

    float acc[8][8];
#pragma unroll
    for (int i = 0; i < 8; i++)
#pragma unroll
        for (int j = 0; j < 8; j++) acc[i][j] = 0.f;

    for (int k0 = 0; k0 < K; k0 += BK) {
        float4 a4 = *(const float4*)(A + (size_t)aRow * K + k0 + aCol);
        float4 b4 = *(const float4*)(Bm + (size_t)(k0 + bRow) * N + bCol);
        As[aCol + 0][aRow] = a4.x;
        As[aCol + 1][aRow] = a4.y;
        As[aCol + 2][aRow] = a4.z;
        As[aCol + 3][aRow] = a4.w;
        *(float4*)&Bs[bRow][bCol] = b4;
        __syncthreads();

#pragma unroll
        for (int kk = 0; kk < BK; kk++) {
            float4 m0v = *(const float4*)&As[kk][tRow * 4];
            float4 m1v = *(const float4*)&As[kk][64 + tRow * 4];
            float4 n0v = *(const float4*)&Bs[kk][tCol * 4];
            float4 n1v = *(const float4*)&Bs[kk][64 + tCol * 4];
            float rM[8] = {m0v.x, m0v.y, m0v.z, m0v.w, m1v.x, m1v.y, m1v.z, m1v.w};
            float rN[8] = {n0v.x, n0v.y, n0v.z, n0v.w, n1v.x, n1v.y, n1v.z, n1v.w};
#pragma unroll
            for (int i = 0; i < 8; i++)
#pragma unroll
                for (int j = 0; j < 8; j++) acc[i][j] += rM[i] * rN[j];
        }
        __syncthreads();
    }

#pragma unroll
    for (int hm = 0; hm < 2; hm++)
#pragma unroll
        for (int ii = 0; ii < 4; ii++) {
            int r = hm * 64 + tRow * 4 + ii;
#pragma unroll
            for (int hn = 0; hn < 2; hn++) {
                int i = hm * 4 + ii;
                float4 o4 = make_float4(acc[i][hn * 4 + 0], acc[i][hn * 4 + 1],
                                        acc[i][hn * 4 + 2], acc[i][hn * 4 + 3]);
                *(float4*)(C + (size_t)r * N + hn * 64 + tCol * 4) = o4;
            }
        }
}

// ---------------------------------------------------------------------------
// RoPE (half-rotation). Each thread handles a (d, d+32) pair -> race-free
// in-place update.
// ---------------------------------------------------------------------------
__global__ void rope_kernel(float* __restrict__ x, const float* __restrict__ cosp,
                            const float* __restrict__ sinp, int nheads)
{
    int idx = blockIdx.x * blockDim.x + threadIdx.x;
    int total = CB * CS * nheads * (CHD / 2);
    if (idx >= total) return;
    int d = idx & 31;                   // 0..31
    int t = idx >> 5;                   // (b,s,h) linear index
    int s = (t / nheads) % CS;
    float* p = x + (size_t)t * CHD;
    float x0 = p[d];
    float x1 = p[d + 32];
    float c0 = cosp[s * CHD + d],      s0 = sinp[s * CHD + d];
    float c1 = cosp[s * CHD + d + 32], s1 = sinp[s * CHD + d + 32];
    p[d]      = x0 * c0 - x1 * s0;      // rot_half[d] = -x[d+32]
    p[d + 32] = x1 * c1 + x0 * s1;      // rot_half[d+32] = x[d]
}

// ---------------------------------------------------------------------------
// Flash attention, fp32. One block per (q-tile of 64, head, batch).
// 256 threads as 16x16 grid, each owns a 4x4 fragment.
// Causal tile skipping: process kv tiles nt <= mt only.
// ---------------------------------------------------------------------------
constexpr int ABM = 64, ABN = 64, KSTR = 68;
constexpr int ATT_SMEM_FLOATS = 2 * 64 * KSTR + 2 * 64 * 64;  // Qt, Kt, Ps, Vs
constexpr int ATT_SMEM_BYTES  = ATT_SMEM_FLOATS * 4;          // 67584

__global__ __launch_bounds__(256) void attn_kernel(
    const float* __restrict__ q, const float* __restrict__ k,
    const float* __restrict__ v, const float* __restrict__ amask,
    float* __restrict__ out)
{
    extern __shared__ float sm[];
    float* Qt = sm;                    // [64][68], k-major (transposed)
    float* Kt = Qt + 64 * KSTR;        // [64][68], k-major
    float* Ps = Kt + 64 * KSTR;        // [64][64], row-major (i, j)
    float* Vs = Ps + 64 * 64;          // [64][64], row-major (j, d)

    const int tid = threadIdx.x;
    const int tx = tid & 15, ty = tid >> 4;
    const int mt = blockIdx.x;
    const int h  = blockIdx.y;
    const int b  = blockIdx.z;
    const int g  = h >> 2;             // R = NH/NKV = 4
    const int m0 = mt * ABM;

    // Load Q tile transposed: Qt[kdim][row]
#pragma unroll
    for (int it = 0; it < 4; it++) {
        int idx = tid + it * 256;
        int row = idx >> 4, c4 = idx & 15;
        const float4 qv = *(const float4*)(
            q + (((size_t)b * CS + m0 + row) * CNH + h) * CHD + c4 * 4);
        Qt[(c4 * 4 + 0) * KSTR + row] = qv.x;
        Qt[(c4 * 4 + 1) * KSTR + row] = qv.y;
        Qt[(c4 * 4 + 2) * KSTR + row] = qv.z;
        Qt[(c4 * 4 + 3) * KSTR + row] = qv.w;
    }

    float m_i[4], l_i[4], acc[4][4];
#pragma unroll
    for (int ii = 0; ii < 4; ii++) {
        m_i[ii] = -1e30f;
        l_i[ii] = 0.f;
#pragma unroll
        for (int dd = 0; dd < 4; dd++) acc[ii][dd] = 0.f;
    }

    for (int nt = 0; nt <= mt; nt++) {
        const int n0 = nt * ABN;
        __syncthreads();  // previous PV done before overwriting Kt/Vs/Ps
#pragma unroll
        for (int it = 0; it < 4; it++) {
            int idx = tid + it * 256;
            int row = idx >> 4, c4 = idx & 15;
            size_t gidx = (((size_t)b * CS + n0 + row) * CNKV + g) * CHD + c4 * 4;
            const float4 kv = *(const float4*)(k + gidx);
            Kt[(c4 * 4 + 0) * KSTR + row] = kv.x;
            Kt[(c4 * 4 + 1) * KSTR + row] = kv.y;
            Kt[(c4 * 4 + 2) * KSTR + row] = kv.z;
            Kt[(c4 * 4 + 3) * KSTR + row] = kv.w;
            *(float4*)(Vs + row * 64 + c4 * 4) = *(const float4*)(v + gidx);
        }
        __syncthreads();

        // S = Q @ K^T fragment (4x4 per thread)
        float s[4][4];
#pragma unroll
        for (int ii = 0; ii < 4; ii++)
#pragma unroll
            for (int jj = 0; jj < 4; jj++) s[ii][jj] = 0.f;

#pragma unroll 16
        for (int kk = 0; kk < 64; kk++) {
            float4 q4 = *(const float4*)(Qt + kk * KSTR + ty * 4);
            float4 k4 = *(const float4*)(Kt + kk * KSTR + tx * 4);
            float qa[4] = {q4.x, q4.y, q4.z, q4.w};
            float ka[4] = {k4.x, k4.y, k4.z, k4.w};
#pragma unroll
            for (int ii = 0; ii < 4; ii++)
#pragma unroll
                for (int jj = 0; jj < 4; jj++) s[ii][jj] += qa[ii] * ka[jj];
        }

        // scale + causal mask + attention-mask bias
        const float scale = 0.125f;  // 1/sqrt(64)
        float bias[4];
#pragma unroll
        for (int jj = 0; jj < 4; jj++)
            bias[jj] = (1.0f - amask[(size_t)b * CS + n0 + tx * 4 + jj]) * -1e9f;

#pragma unroll
        for (int ii = 0; ii < 4; ii++) {
            int ig = m0 + ty * 4 + ii;
#pragma unroll
            for (int jj = 0; jj < 4; jj++) {
                int jg = n0 + tx * 4 + jj;
                float val = s[ii][jj] * scale;
                if (jg > ig) val = -1e30f;
                s[ii][jj] = val + bias[jj];
            }
        }

        // online softmax (row reductions across the 16 tx lanes of each group)
#pragma unroll
        for (int ii = 0; ii < 4; ii++) {
            float rmax = fmaxf(fmaxf(s[ii][0], s[ii][1]), fmaxf(s[ii][2], s[ii][3]));
#pragma unroll
            for (int off = 8; off; off >>= 1)
                rmax = fmaxf(rmax, __shfl_xor_sync(0xffffffffu, rmax, off));
            float nm = fmaxf(m_i[ii], rmax);
            float corr = __expf(m_i[ii] - nm);
            m_i[ii] = nm;
            float rs = 0.f;
#pragma unroll
            for (int jj = 0; jj < 4; jj++) {
                float p = __expf(s[ii][jj] - nm);
                s[ii][jj] = p;
                rs += p;
            }
#pragma unroll
            for (int off = 8; off; off >>= 1)
                rs += __shfl_xor_sync(0xffffffffu, rs, off);
            l_i[ii] = l_i[ii] * corr + rs;
#pragma unroll
            for (int dd = 0; dd < 4; dd++) acc[ii][dd] *= corr;
        }

        // stage P to smem (all threads done with previous Ps since tile start)
#pragma unroll
        for (int ii = 0; ii < 4; ii++) {
            float4 p4 = make_float4(s[ii][0], s[ii][1], s[ii][2], s[ii][3]);
            *(float4*)(Ps + (ty * 4 + ii) * 64 + tx * 4) = p4;
        }
        __syncthreads();

        // acc += P @ V
#pragma unroll 8
        for (int j = 0; j < 64; j++) {
            float4 v4 = *(const float4*)(Vs + j * 64 + tx * 4);
            float va[4] = {v4.x, v4.y, v4.z, v4.w};
#pragma unroll
            for (int ii = 0; ii < 4; ii++) {
                float p = Ps[(ty * 4 + ii) * 64 + j];
#pragma unroll
                for (int dd = 0; dd < 4; dd++) acc[ii][dd] += p * va[dd];
            }
        }
    }

    // normalize and write (B, S, NH, HD)
#pragma unroll
    for (int ii = 0; ii < 4; ii++) {
        float inv = 1.0f / l_i[ii];
        float4 o4 = make_float4(acc[ii][0] * inv, acc[ii][1] * inv,
                                acc[ii][2] * inv, acc[ii][3] * inv);
        *(float4*)(out + (((size_t)b * CS + m0 + ty * 4 + ii) * CNH + h) * CHD + tx * 4) = o4;
    }
}

// ---------------------------------------------------------------------------
extern "C" void kernel_launch(void* const* d_in, const int* in_sizes, int n_in,
                              void* d_out, int out_size)
{
    const float* x     = (const float*)d_in[0];
    const float* cosp  = (const float*)d_in[1];
    const float* sinp  = (const float*)d_in[2];
    const float* amask = (const float*)d_in[3];
    const float* Wq    = (const float*)d_in[4];
    const float* Wk    = (const float*)d_in[5];
    const float* Wv    = (const float*)d_in[6];
    const float* Wo    = (const float*)d_in[7];
    float* out = (float*)d_out;

    float *qb, *kb, *vb, *ab;
    cudaGetSymbolAddress((void**)&qb, g_q);
    cudaGetSymbolAddress((void**)&kb, g_k);
    cudaGetSymbolAddress((void**)&vb, g_v);
    cudaGetSymbolAddress((void**)&ab, g_attn);

    // QKV projections
    sgemm_kernel<<<dim3(CNH * CHD / 128, CM / 128), 256>>>(CM, CNH * CHD, CH, x, Wq, qb);
    sgemm_kernel<<<dim3(CNKV * CHD / 128, CM / 128), 256>>>(CM, CNKV * CHD, CH, x, Wk, kb);
    sgemm_kernel<<<dim3(CNKV * CHD / 128, CM / 128), 256>>>(CM, CNKV * CHD, CH, x, Wv, vb);

    // RoPE on q and k
    {
        int nq = CB * CS * CNH * (CHD / 2);
        rope_kernel<<<(nq + 255) / 256, 256>>>(qb, cosp, sinp, CNH);
        int nk = CB * CS * CNKV * (CHD / 2);
        rope_kernel<<<(nk + 255) / 256, 256>>>(kb, cosp, sinp, CNKV);
    }

    // Attention
    cudaFuncSetAttribute(attn_kernel, cudaFuncAttributeMaxDynamicSharedMemorySize,
                         ATT_SMEM_BYTES);
    attn_kernel<<<dim3(CS / ABM, CNH, CB), 256, ATT_SMEM_BYTES>>>(qb, kb, vb, amask, ab);

    // Output projection
    sgemm_kernel<<<dim3(CH / 128, CM / 128), 256>>>(CM, CH, CNH * CHD, ab, Wo, out);
}